// round 3
// baseline (speedup 1.0000x reference)
#include <cuda_runtime.h>
#include <cuda_bf16.h>
#include <cstdint>
#include <cstddef>

#define NPTS 80000
#define H    32
#define KPTS 15
#define CIN  128
#define COUT 256
#define D2   64
#define INFL 0.4f
#define EPS  1e-5f
#define SLOPE 0.2f

typedef __nv_bfloat16 bf16;
typedef __nv_bfloat162 bf162;

// ---------------- device scratch ----------------
__device__ __align__(128) bf16  g_fh [(size_t)NPTS * CIN];          // feats hi
__device__ __align__(128) bf16  g_fl [(size_t)NPTS * CIN];          // feats lo
__device__ __align__(128) float g_x1 [(size_t)NPTS * D2];           // unary_1 out (fp32)
__device__ __align__(128) bf16  g_fkh[(size_t)NPTS * KPTS * D2];    // fk hi
__device__ __align__(128) bf16  g_fkl[(size_t)NPTS * KPTS * D2];    // fk lo
__device__ __align__(128) bf16  g_xkh[(size_t)NPTS * D2];           // x_kp hi
__device__ __align__(128) bf16  g_xkl[(size_t)NPTS * D2];           // x_kp lo
__device__ __align__(128) float g_y2 [(size_t)NPTS * COUT];         // unary_2 pre-BN
__device__ __align__(128) float g_part[256 * 2 * COUT];
__device__ __align__(128) float g_bn1 [2 * D2];
__device__ __align__(128) float g_bn2 [2 * COUT];
__device__ __align__(128) float g_bnsc[2 * COUT];
// transposed + split weights (K-major [N x K])
__device__ __align__(128) bf16  g_w1h[D2 * CIN],     g_w1l[D2 * CIN];
__device__ __align__(128) bf16  g_kwh[D2 * KPTS*D2], g_kwl[D2 * KPTS*D2];
__device__ __align__(128) bf16  g_w2h[COUT * D2],    g_w2l[COUT * D2];
__device__ __align__(128) bf16  g_wsh[COUT * CIN],   g_wsl[COUT * CIN];

__device__ __forceinline__ float leaky(float v) { return v > 0.f ? v : v * SLOPE; }

// ---------------- mma.sync bf16 GEMM (portable HMMA path) ----------------
// C[M x ND] = (Ah+Al) @ (Bh+Bl)^T, B stored K-major [ND x KD] row-major.
// 3 K-segments: Ah*Bh + Ah*Bl + Al*Bh, all in fp32 register accumulators.
// Block: 256 thr = 8 warps, tile 128(M) x 64(N); warp tile 32x32.
template<int KD, int ND, int EMIT>   // EMIT 0: fp32 C; 1: bf16 hi/lo (Ch/Cl)
__global__ __launch_bounds__(256)
void gemm_mma(const bf16* __restrict__ Ah, const bf16* __restrict__ Al,
              const bf16* __restrict__ Bh, const bf16* __restrict__ Bl,
              float* __restrict__ C, bf16* __restrict__ Ch, bf16* __restrict__ Cl) {
    __shared__ bf16 sA[128][40];   // 32 k + 8 pad
    __shared__ bf16 sB[64][40];

    const int tid  = threadIdx.x;
    const int wid  = tid >> 5;
    const int lane = tid & 31;
    const int row0 = blockIdx.x * 128;
    const int col0 = blockIdx.y * 64;
    const int wm   = (wid >> 1) * 32;       // warp m offset in tile
    const int wn   = (wid & 1) * 32;        // warp n offset in tile

    float acc[2][4][4];
#pragma unroll
    for (int mt = 0; mt < 2; mt++)
#pragma unroll
        for (int nt = 0; nt < 4; nt++)
#pragma unroll
            for (int q = 0; q < 4; q++) acc[mt][nt][q] = 0.f;

    const int lg = lane >> 2;       // 0..7
    const int lq = lane & 3;        // 0..3

    constexpr int NT = KD / 32;
    for (int seg = 0; seg < 3; seg++) {
        const bf16* As = (seg == 2) ? Al : Ah;
        const bf16* Bs = (seg == 1) ? Bl : Bh;
        for (int kt = 0; kt < NT; kt++) {
            const int k0 = kt * 32;
            // load A tile: 128 rows x 32 k -> 512 uint4, 2 per thread
            {
                const int idx0 = tid;            // chunk ids
                const int r0 = idx0 >> 2, c0 = idx0 & 3;
                uint4 va = *(const uint4*)&As[(size_t)(row0 + r0) * KD + k0 + c0 * 8];
                const int idx1 = tid + 256;
                const int r1 = idx1 >> 2, c1 = idx1 & 3;
                uint4 vb = *(const uint4*)&As[(size_t)(row0 + r1) * KD + k0 + c1 * 8];
                // B tile: 64 rows x 32 k -> 256 uint4, 1 per thread
                const int rb = tid >> 2, cb = tid & 3;
                uint4 vc = *(const uint4*)&Bs[(size_t)(col0 + rb) * KD + k0 + cb * 8];
                __syncthreads();   // protect previous iter's reads
                *(uint4*)&sA[r0][c0 * 8] = va;
                *(uint4*)&sA[r1][c1 * 8] = vb;
                *(uint4*)&sB[rb][cb * 8] = vc;
            }
            __syncthreads();
            // compute: 2 k16-steps
#pragma unroll
            for (int ks = 0; ks < 2; ks++) {
                const int kk = ks * 16 + lq * 2;
                uint32_t afr[2][4];
#pragma unroll
                for (int mt = 0; mt < 2; mt++) {
                    const int r = wm + mt * 16 + lg;
                    afr[mt][0] = *(const uint32_t*)&sA[r][kk];
                    afr[mt][1] = *(const uint32_t*)&sA[r + 8][kk];
                    afr[mt][2] = *(const uint32_t*)&sA[r][kk + 8];
                    afr[mt][3] = *(const uint32_t*)&sA[r + 8][kk + 8];
                }
                uint32_t bfr[4][2];
#pragma unroll
                for (int nt = 0; nt < 4; nt++) {
                    const int n = wn + nt * 8 + lg;
                    bfr[nt][0] = *(const uint32_t*)&sB[n][kk];
                    bfr[nt][1] = *(const uint32_t*)&sB[n][kk + 8];
                }
#pragma unroll
                for (int mt = 0; mt < 2; mt++)
#pragma unroll
                    for (int nt = 0; nt < 4; nt++) {
                        asm volatile(
                            "mma.sync.aligned.m16n8k16.row.col.f32.bf16.bf16.f32 "
                            "{%0,%1,%2,%3}, {%4,%5,%6,%7}, {%8,%9}, {%0,%1,%2,%3};"
                            : "+f"(acc[mt][nt][0]), "+f"(acc[mt][nt][1]),
                              "+f"(acc[mt][nt][2]), "+f"(acc[mt][nt][3])
                            : "r"(afr[mt][0]), "r"(afr[mt][1]), "r"(afr[mt][2]), "r"(afr[mt][3]),
                              "r"(bfr[nt][0]), "r"(bfr[nt][1]));
                    }
            }
        }
    }

    // epilogue
#pragma unroll
    for (int mt = 0; mt < 2; mt++) {
#pragma unroll
        for (int nt = 0; nt < 4; nt++) {
            const int r  = row0 + wm + mt * 16 + lg;
            const int cc = col0 + wn + nt * 8 + lq * 2;
            if (EMIT == 0) {
                *(float2*)&C[(size_t)r * ND + cc] =
                    make_float2(acc[mt][nt][0], acc[mt][nt][1]);
                *(float2*)&C[(size_t)(r + 8) * ND + cc] =
                    make_float2(acc[mt][nt][2], acc[mt][nt][3]);
            } else {
#pragma unroll
                for (int half = 0; half < 2; half++) {
                    const float v0 = acc[mt][nt][half * 2 + 0];
                    const float v1 = acc[mt][nt][half * 2 + 1];
                    const int rr = r + half * 8;
                    bf162 hh, ll;
                    hh.x = __float2bfloat16(v0); hh.y = __float2bfloat16(v1);
                    ll.x = __float2bfloat16(v0 - __bfloat162float(hh.x));
                    ll.y = __float2bfloat16(v1 - __bfloat162float(hh.y));
                    *(bf162*)&Ch[(size_t)rr * ND + cc] = hh;
                    *(bf162*)&Cl[(size_t)rr * ND + cc] = ll;
                }
            }
        }
    }
}

// ---------------- fp32 -> bf16 hi/lo split ----------------
__global__ __launch_bounds__(256)
void split_kernel(const float* __restrict__ X, bf16* __restrict__ Xh, bf16* __restrict__ Xl) {
    const size_t i = (size_t)blockIdx.x * 256 + threadIdx.x;
    const float4 v = ((const float4*)X)[i];
    bf162 h0, h1, l0, l1;
    h0.x = __float2bfloat16(v.x); h0.y = __float2bfloat16(v.y);
    h1.x = __float2bfloat16(v.z); h1.y = __float2bfloat16(v.w);
    l0.x = __float2bfloat16(v.x - __bfloat162float(h0.x));
    l0.y = __float2bfloat16(v.y - __bfloat162float(h0.y));
    l1.x = __float2bfloat16(v.z - __bfloat162float(h1.x));
    l1.y = __float2bfloat16(v.w - __bfloat162float(h1.y));
    ((bf162*)Xh)[i * 2 + 0] = h0; ((bf162*)Xh)[i * 2 + 1] = h1;
    ((bf162*)Xl)[i * 2 + 0] = l0; ((bf162*)Xl)[i * 2 + 1] = l1;
}

// ---------------- transpose + split weights: B[K x N] -> T[N x K] ----------------
__global__ void tsplit_kernel(const float* __restrict__ B, bf16* __restrict__ Th,
                              bf16* __restrict__ Tl, int K, int N) {
    const int idx = blockIdx.x * 256 + threadIdx.x;
    if (idx >= K * N) return;
    const int k = idx / N, n = idx % N;
    const float v = B[idx];
    const bf16 h = __float2bfloat16(v);
    Th[(size_t)n * K + k] = h;
    Tl[(size_t)n * K + k] = __float2bfloat16(v - __bfloat162float(h));
}

// ---------------- column stats (deterministic 2-stage) ----------------
template<int C>
__global__ __launch_bounds__(256)
void colstats(const float* __restrict__ y, float* __restrict__ part) {
    const int tid = threadIdx.x, bid = blockIdx.x;
    if (C == 256) {
        float s = 0.f, q = 0.f;
        for (int r = bid; r < NPTS; r += 256) {
            float v = y[(size_t)r * 256 + tid];
            s += v; q += v * v;
        }
        part[bid * 512 + tid] = s;
        part[bid * 512 + 256 + tid] = q;
    } else {
        const int c = tid & 63, rg = tid >> 6;
        float s = 0.f, q = 0.f;
        for (int r = bid * 4 + rg; r < NPTS; r += 1024) {
            float v = y[(size_t)r * 64 + c];
            s += v; q += v * v;
        }
        __shared__ float sh[2][256];
        sh[0][tid] = s; sh[1][tid] = q;
        __syncthreads();
        if (tid < 64) {
            s = sh[0][tid] + sh[0][tid + 64] + sh[0][tid + 128] + sh[0][tid + 192];
            q = sh[1][tid] + sh[1][tid + 64] + sh[1][tid + 128] + sh[1][tid + 192];
            part[bid * 128 + tid] = s;
            part[bid * 128 + 64 + tid] = q;
        }
    }
}

template<int C>
__global__ void finalize_bn(const float* __restrict__ part,
                            const float* __restrict__ g, const float* __restrict__ b,
                            float* __restrict__ bnout) {
    const int c = threadIdx.x;
    float s = 0.f, q = 0.f;
    for (int i = 0; i < 256; i++) {
        s += part[i * 2 * C + c];
        q += part[i * 2 * C + C + c];
    }
    const float mean = s / (float)NPTS;
    const float var = q / (float)NPTS - mean * mean;
    const float sc = g[c] * rsqrtf(var + EPS);
    bnout[c] = sc;
    bnout[C + c] = b[c] - mean * sc;
}

// ---------------- BN1 apply + leaky relu (in place on g_x1) ----------------
__global__ __launch_bounds__(256)
void bn_act_64(float* __restrict__ x, const float* __restrict__ bn) {
    const size_t i = (size_t)blockIdx.x * 256 + threadIdx.x;
    float4 v = ((float4*)x)[i];
    const int c = (int)((i * 4) & 63);
    v.x = leaky(v.x * bn[c + 0] + bn[64 + c + 0]);
    v.y = leaky(v.y * bn[c + 1] + bn[64 + c + 1]);
    v.z = leaky(v.z * bn[c + 2] + bn[64 + c + 2]);
    v.w = leaky(v.w * bn[c + 3] + bn[64 + c + 3]);
    ((float4*)x)[i] = v;
}

// ---------------- packed f32x2 FMA helpers ----------------
__device__ __forceinline__ unsigned long long pack2(float a, float b) {
    unsigned long long p;
    asm("mov.b64 %0, {%1, %2};" : "=l"(p) : "f"(a), "f"(b));
    return p;
}
__device__ __forceinline__ void unpack2(unsigned long long p, float& a, float& b) {
    asm("mov.b64 {%0, %1}, %2;" : "=f"(a), "=f"(b) : "l"(p));
}
__device__ __forceinline__ void ffma2(unsigned long long& acc,
                                      unsigned long long w2, unsigned long long v2) {
    asm("fma.rn.f32x2 %0, %1, %2, %0;" : "+l"(acc) : "l"(w2), "l"(v2));
}

// ---------------- KPConv: influence weights + fk accumulation ----------------
__global__ __launch_bounds__(256)
void kpconv_kernel(const float* __restrict__ xyz, const int* __restrict__ nbr,
                   const float* __restrict__ kp) {
    __shared__ float s_kp[KPTS * 3];
    __shared__ int   s_nbr[16][H];
    __shared__ float s_w[16 * 481];

    const int tid = threadIdx.x;
    const int n0 = blockIdx.x * 16;

    if (tid < KPTS * 3) s_kp[tid] = kp[tid];
    __syncthreads();

    for (int t = tid; t < 512; t += 256) {
        const int p = t >> 5, h = t & 31;
        const int n = n0 + p;
        const int j = nbr[n * H + h];
        s_nbr[p][h] = j;
        const float dx = xyz[j * 3 + 0] - xyz[n * 3 + 0];
        const float dy = xyz[j * 3 + 1] - xyz[n * 3 + 1];
        const float dz = xyz[j * 3 + 2] - xyz[n * 3 + 2];
        float* wp = &s_w[p * 481 + h * 15];
#pragma unroll
        for (int k = 0; k < KPTS; k++) {
            const float ex = dx - s_kp[k * 3 + 0];
            const float ey = dy - s_kp[k * 3 + 1];
            const float ez = dz - s_kp[k * 3 + 2];
            const float sq = ex * ex + ey * ey + ez * ez;
            wp[k] = fmaxf(1.f - sqrtf(sq) * (1.f / INFL), 0.f);
        }
    }
    __syncthreads();

    const int p = tid >> 4;
    const int d0 = (tid & 15) * 4;
    const int n = n0 + p;
    unsigned long long acc0[KPTS], acc1[KPTS];
#pragma unroll
    for (int k = 0; k < KPTS; k++) { acc0[k] = 0ull; acc1[k] = 0ull; }
    const float* wrow = &s_w[p * 481];
    for (int h = 0; h < H; h++) {
        const int j = s_nbr[p][h];
        const float4 v = *(const float4*)&g_x1[(size_t)j * 64 + d0];
        const unsigned long long v01 = pack2(v.x, v.y);
        const unsigned long long v23 = pack2(v.z, v.w);
        const float* wp = wrow + h * 15;
#pragma unroll
        for (int k = 0; k < KPTS; k++) {
            const float w = wp[k];
            const unsigned long long w2 = pack2(w, w);
            ffma2(acc0[k], w2, v01);
            ffma2(acc1[k], w2, v23);
        }
    }
    bf16* dh = &g_fkh[(size_t)n * (KPTS * 64) + d0];
    bf16* dl = &g_fkl[(size_t)n * (KPTS * 64) + d0];
#pragma unroll
    for (int k = 0; k < KPTS; k++) {
        float a0, a1, a2, a3;
        unpack2(acc0[k], a0, a1);
        unpack2(acc1[k], a2, a3);
        bf162 h01, h23, l01, l23;
        h01.x = __float2bfloat16(a0); h01.y = __float2bfloat16(a1);
        h23.x = __float2bfloat16(a2); h23.y = __float2bfloat16(a3);
        l01.x = __float2bfloat16(a0 - __bfloat162float(h01.x));
        l01.y = __float2bfloat16(a1 - __bfloat162float(h01.y));
        l23.x = __float2bfloat16(a2 - __bfloat162float(h23.x));
        l23.y = __float2bfloat16(a3 - __bfloat162float(h23.y));
        *(bf162*)&dh[k * 64 + 0] = h01; *(bf162*)&dh[k * 64 + 2] = h23;
        *(bf162*)&dl[k * 64 + 0] = l01; *(bf162*)&dl[k * 64 + 2] = l23;
    }
}

// ---------------- final combine ----------------
__global__ __launch_bounds__(256)
void combine_kernel(const float* __restrict__ y2, float* __restrict__ out,
                    const float* __restrict__ bn2, const float* __restrict__ bnsc) {
    const size_t i = (size_t)blockIdx.x * 256 + threadIdx.x;
    const int c = (int)((i * 4) & 255);
    float4 a = ((const float4*)y2)[i];
    float4 s = ((float4*)out)[i];
    float4 r;
    r.x = leaky(a.x * bn2[c + 0] + bn2[256 + c + 0]) + (s.x * bnsc[c + 0] + bnsc[256 + c + 0]);
    r.y = leaky(a.y * bn2[c + 1] + bn2[256 + c + 1]) + (s.y * bnsc[c + 1] + bnsc[256 + c + 1]);
    r.z = leaky(a.z * bn2[c + 2] + bn2[256 + c + 2]) + (s.z * bnsc[c + 2] + bnsc[256 + c + 2]);
    r.w = leaky(a.w * bn2[c + 3] + bn2[256 + c + 3]) + (s.w * bnsc[c + 3] + bnsc[256 + c + 3]);
    ((float4*)out)[i] = r;
}

// ---------------- launcher ----------------
extern "C" void kernel_launch(void* const* d_in, const int* in_sizes, int n_in,
                              void* d_out, int out_size) {
    const float* feats = (const float*)d_in[0];
    const float* xyz   = (const float*)d_in[1];
    const int*   nbr   = (const int*)d_in[3];
    const float* W1    = (const float*)d_in[4];
    const float* g1    = (const float*)d_in[5];
    const float* b1    = (const float*)d_in[6];
    const float* kpp   = (const float*)d_in[7];
    const float* kpw   = (const float*)d_in[8];
    const float* W2    = (const float*)d_in[9];
    const float* g2    = (const float*)d_in[10];
    const float* b2    = (const float*)d_in[11];
    const float* Wsc   = (const float*)d_in[12];
    const float* gsc   = (const float*)d_in[13];
    const float* bsc   = (const float*)d_in[14];
    float* out = (float*)d_out;

    void *pfh, *pfl, *px1, *pfkh, *pfkl, *pxkh, *pxkl, *py2, *ppart, *pbn1, *pbn2, *pbnsc;
    void *pw1h, *pw1l, *pkwh, *pkwl, *pw2h, *pw2l, *pwsh, *pwsl;
    cudaGetSymbolAddress(&pfh, g_fh);   cudaGetSymbolAddress(&pfl, g_fl);
    cudaGetSymbolAddress(&px1, g_x1);
    cudaGetSymbolAddress(&pfkh, g_fkh); cudaGetSymbolAddress(&pfkl, g_fkl);
    cudaGetSymbolAddress(&pxkh, g_xkh); cudaGetSymbolAddress(&pxkl, g_xkl);
    cudaGetSymbolAddress(&py2, g_y2);   cudaGetSymbolAddress(&ppart, g_part);
    cudaGetSymbolAddress(&pbn1, g_bn1); cudaGetSymbolAddress(&pbn2, g_bn2);
    cudaGetSymbolAddress(&pbnsc, g_bnsc);
    cudaGetSymbolAddress(&pw1h, g_w1h); cudaGetSymbolAddress(&pw1l, g_w1l);
    cudaGetSymbolAddress(&pkwh, g_kwh); cudaGetSymbolAddress(&pkwl, g_kwl);
    cudaGetSymbolAddress(&pw2h, g_w2h); cudaGetSymbolAddress(&pw2l, g_w2l);
    cudaGetSymbolAddress(&pwsh, g_wsh); cudaGetSymbolAddress(&pwsl, g_wsl);

    bf16 *fh = (bf16*)pfh, *fl = (bf16*)pfl;
    float *x1 = (float*)px1, *y2 = (float*)py2, *part = (float*)ppart;
    bf16 *fkh = (bf16*)pfkh, *fkl = (bf16*)pfkl, *xkh = (bf16*)pxkh, *xkl = (bf16*)pxkl;
    float *bn1 = (float*)pbn1, *bn2 = (float*)pbn2, *bnsc = (float*)pbnsc;
    bf16 *w1h = (bf16*)pw1h, *w1l = (bf16*)pw1l, *kwh = (bf16*)pkwh, *kwl = (bf16*)pkwl;
    bf16 *w2h = (bf16*)pw2h, *w2l = (bf16*)pw2l, *wsh = (bf16*)pwsh, *wsl = (bf16*)pwsl;

    // 0) splits / transposes
    split_kernel<<<NPTS * CIN / 4 / 256, 256>>>(feats, fh, fl);
    tsplit_kernel<<<(CIN * D2 + 255) / 256, 256>>>(W1, w1h, w1l, CIN, D2);
    tsplit_kernel<<<(KPTS * D2 * D2 + 255) / 256, 256>>>(kpw, kwh, kwl, KPTS * D2, D2);
    tsplit_kernel<<<(D2 * COUT + 255) / 256, 256>>>(W2, w2h, w2l, D2, COUT);
    tsplit_kernel<<<(CIN * COUT + 255) / 256, 256>>>(Wsc, wsh, wsl, CIN, COUT);

    // 1) unary_1: x1 = feats @ W1  [N,64]
    gemm_mma<128, 64, 0><<<dim3(625, 1), 256>>>(fh, fl, w1h, w1l, x1, nullptr, nullptr);
    // 2) BN1 + act
    colstats<64><<<256, 256>>>(x1, part);
    finalize_bn<64><<<1, 64>>>(part, g1, b1, bn1);
    bn_act_64<<<NPTS * 64 / 4 / 256, 256>>>(x1, bn1);
    // 3) KPConv -> fk (bf16 hi/lo)
    kpconv_kernel<<<NPTS / 16, 256>>>(xyz, nbr, kpp);
    // 4) x_kp = fk @ kp_weights [N,960]@[960,64], emit bf16 hi/lo
    gemm_mma<960, 64, 1><<<dim3(625, 1), 256>>>(fkh, fkl, kwh, kwl, nullptr, xkh, xkl);
    // 5) y2 = x_kp @ W2  [N,256]
    gemm_mma<64, 256, 0><<<dim3(625, 4), 256>>>(xkh, xkl, w2h, w2l, y2, nullptr, nullptr);
    colstats<256><<<256, 256>>>(y2, part);
    finalize_bn<256><<<1, 256>>>(part, g2, b2, bn2);
    // 6) shortcut -> out raw
    gemm_mma<128, 256, 0><<<dim3(625, 4), 256>>>(fh, fl, wsh, wsl, out, nullptr, nullptr);
    colstats<256><<<256, 256>>>(out, part);
    finalize_bn<256><<<1, 256>>>(part, gsc, bsc, bnsc);
    // 7) combine
    combine_kernel<<<NPTS * 256 / 4 / 256, 256>>>(y2, out, bn2, bnsc);
}